// round 12
// baseline (speedup 1.0000x reference)
#include <cuda_runtime.h>

#define BATCH 2048
#define IN 256
#define OUT 256
#define OT 16   // outputs per block
#define BT 4    // batches per block

// Folded affine coefficients: postact = c1*x + c0
__device__ float g_c1[OUT * IN];
__device__ float g_c0[OUT * IN];

// Vectorized precompute: each thread folds 4 consecutive (o,i) elements.
__global__ __launch_bounds__(128) void kan_precompute(const float4* __restrict__ affine,
                                                      const float4* __restrict__ mask) {
    // Let the dependent kan_main launch immediately; its grid-dependency sync
    // still waits for this grid's completion before reading g_c1/g_c0.
    cudaTriggerProgrammaticLaunchCompletion();

    int v = blockIdx.x * blockDim.x + threadIdx.x;   // float4 index, 0..16383
    float4 m4 = mask[v];
    float4 a0 = affine[4 * v + 0];
    float4 a1 = affine[4 * v + 1];
    float4 a2 = affine[4 * v + 2];
    float4 a3 = affine[4 * v + 3];

    float4 c1, c0;
    c1.x = m4.x * a0.z * a0.x;  c0.x = m4.x * fmaf(a0.z, a0.y, a0.w);
    c1.y = m4.y * a1.z * a1.x;  c0.y = m4.y * fmaf(a1.z, a1.y, a1.w);
    c1.z = m4.z * a2.z * a2.x;  c0.z = m4.z * fmaf(a2.z, a2.y, a2.w);
    c1.w = m4.w * a3.z * a3.x;  c0.w = m4.w * fmaf(a3.z, a3.y, a3.w);

    reinterpret_cast<float4*>(g_c1)[v] = c1;
    reinterpret_cast<float4*>(g_c0)[v] = c0;
}

__global__ __launch_bounds__(256) void kan_main(const float* __restrict__ x,
                                                float* __restrict__ y,
                                                float* __restrict__ post) {
    __shared__ float4 xs[BT * (IN / 4)];  // 4 batches x 64 float4 = 4 KB

    const int t = threadIdx.x;
    const int o_loc = t >> 4;      // 0..15
    const int lane = t & 15;       // 0..15
    const int o = blockIdx.y * OT + o_loc;
    const int b0 = blockIdx.x * BT;

    // x tile load does NOT depend on the precompute — do it before the grid
    // sync so it overlaps the tail of kan_precompute. 256 float4s, 1/thread.
    const float4* xg = reinterpret_cast<const float4*>(x + (size_t)b0 * IN);
    xs[t] = xg[t];

    // Wait for kan_precompute's grid to complete before reading g_c1/g_c0.
    cudaGridDependencySynchronize();
    __syncthreads();

    // This thread's 16-coefficient slice, reused for all BT batches.
    float4 c1r[4], c0r[4];
#pragma unroll
    for (int k = 0; k < 4; k++) {
        int f = lane + 16 * k;
        c1r[k] = reinterpret_cast<const float4*>(g_c1)[o * (IN / 4) + f];
        c0r[k] = reinterpret_cast<const float4*>(g_c0)[o * (IN / 4) + f];
    }

#pragma unroll
    for (int bl = 0; bl < BT; bl++) {
        const int b = b0 + bl;
        float4* prow = reinterpret_cast<float4*>(post + ((size_t)b * OUT + o) * IN);
        float acc = 0.0f;
#pragma unroll
        for (int k = 0; k < 4; k++) {
            float4 xv = xs[bl * (IN / 4) + lane + 16 * k];
            float4 p;
            p.x = fmaf(c1r[k].x, xv.x, c0r[k].x);
            p.y = fmaf(c1r[k].y, xv.y, c0r[k].y);
            p.z = fmaf(c1r[k].z, xv.z, c0r[k].z);
            p.w = fmaf(c1r[k].w, xv.w, c0r[k].w);
            acc += (p.x + p.y) + (p.z + p.w);
            // Write-through streaming store: no L2 dirty-line allocation for a
            // never-re-read output stream; 16 lanes -> contiguous 256B runs.
            __stwt(&prow[lane + 16 * k], p);
        }
#pragma unroll
        for (int off = 8; off; off >>= 1)
            acc += __shfl_xor_sync(0xffffffffu, acc, off);
        if (lane == 0) y[(size_t)b * OUT + o] = acc;
    }
}

extern "C" void kernel_launch(void* const* d_in, const int* in_sizes, int n_in,
                              void* d_out, int out_size) {
    const float* x      = (const float*)d_in[0];  // [2048, 256]
    const float* affine = (const float*)d_in[1];  // [256, 256, 4]
    const float* mask   = (const float*)d_in[2];  // [256, 256]

    float* y    = (float*)d_out;                        // [2048, 256]
    float* post = (float*)d_out + (size_t)BATCH * OUT;  // [2048, 256, 256]

    kan_precompute<<<(OUT * IN) / (128 * 4), 128>>>((const float4*)affine,
                                                    (const float4*)mask);

    // PDL launch: kan_main begins launching while kan_precompute runs; the
    // in-kernel cudaGridDependencySynchronize() enforces the data dependency.
    cudaLaunchConfig_t cfg = {};
    cfg.gridDim = dim3(BATCH / BT, OUT / OT);   // (512, 16) = 8192 blocks
    cfg.blockDim = dim3(256, 1, 1);
    cfg.dynamicSmemBytes = 0;
    cfg.stream = 0;
    cudaLaunchAttribute attr[1];
    attr[0].id = cudaLaunchAttributeProgrammaticStreamSerialization;
    attr[0].val.programmaticStreamSerializationAllowed = 1;
    cfg.attrs = attr;
    cfg.numAttrs = 1;
    cudaLaunchKernelEx(&cfg, kan_main, x, y, post);
}

// round 13
// speedup vs baseline: 1.0657x; 1.0657x over previous
#include <cuda_runtime.h>

#define BATCH 2048
#define IN 256
#define OUT 256
#define OT 16   // outputs per block
#define BT 4    // batches per block

// Folded affine coefficients: postact = c1*x + c0
__device__ float g_c1[OUT * IN];
__device__ float g_c0[OUT * IN];

// Vectorized precompute: each thread folds 4 consecutive (o,i) elements.
// 16384 threads = 64 blocks; coalesced 64B affine reads, float4 stores.
__global__ __launch_bounds__(256) void kan_precompute(const float4* __restrict__ affine,
                                                      const float4* __restrict__ mask) {
    // Let the dependent kan_main launch immediately; its grid-dependency sync
    // still waits for this grid's completion before reading g_c1/g_c0.
    cudaTriggerProgrammaticLaunchCompletion();

    int v = blockIdx.x * blockDim.x + threadIdx.x;   // float4 index, 0..16383
    float4 m4 = mask[v];
    const float mm[4] = {m4.x, m4.y, m4.z, m4.w};
    float c1v[4], c0v[4];
#pragma unroll
    for (int q = 0; q < 4; q++) {
        float4 a = affine[4 * v + q];                // (a0,a1,a2,a3)
        c1v[q] = mm[q] * a.z * a.x;
        c0v[q] = mm[q] * fmaf(a.z, a.y, a.w);
    }
    reinterpret_cast<float4*>(g_c1)[v] = make_float4(c1v[0], c1v[1], c1v[2], c1v[3]);
    reinterpret_cast<float4*>(g_c0)[v] = make_float4(c0v[0], c0v[1], c0v[2], c0v[3]);
}

__global__ __launch_bounds__(256) void kan_main(const float* __restrict__ x,
                                                float* __restrict__ y,
                                                float* __restrict__ post) {
    __shared__ float4 xs[BT * (IN / 4)];  // 4 batches x 64 float4 = 4 KB

    const int t = threadIdx.x;
    const int o_loc = t >> 4;      // 0..15
    const int lane = t & 15;       // 0..15
    const int o = blockIdx.y * OT + o_loc;
    const int b0 = blockIdx.x * BT;

    // x tile load does NOT depend on the precompute — do it before the grid
    // sync so it overlaps the tail of kan_precompute. 256 float4s, 1/thread.
    const float4* xg = reinterpret_cast<const float4*>(x + (size_t)b0 * IN);
    xs[t] = xg[t];

    // Wait for kan_precompute's grid to complete before reading g_c1/g_c0.
    cudaGridDependencySynchronize();
    __syncthreads();

    // This thread's 16-coefficient slice, reused for all BT batches.
    float4 c1r[4], c0r[4];
#pragma unroll
    for (int k = 0; k < 4; k++) {
        int f = lane + 16 * k;
        c1r[k] = reinterpret_cast<const float4*>(g_c1)[o * (IN / 4) + f];
        c0r[k] = reinterpret_cast<const float4*>(g_c0)[o * (IN / 4) + f];
    }

#pragma unroll
    for (int bl = 0; bl < BT; bl++) {
        const int b = b0 + bl;
        float4* prow = reinterpret_cast<float4*>(post + ((size_t)b * OUT + o) * IN);
        float acc = 0.0f;
#pragma unroll
        for (int k = 0; k < 4; k++) {
            float4 xv = xs[bl * (IN / 4) + lane + 16 * k];
            float4 p;
            p.x = fmaf(c1r[k].x, xv.x, c0r[k].x);
            p.y = fmaf(c1r[k].y, xv.y, c0r[k].y);
            p.z = fmaf(c1r[k].z, xv.z, c0r[k].z);
            p.w = fmaf(c1r[k].w, xv.w, c0r[k].w);
            acc += (p.x + p.y) + (p.z + p.w);
            // 16 lanes with consecutive f -> contiguous 256B run, evict-first.
            __stcs(&prow[lane + 16 * k], p);
        }
#pragma unroll
        for (int off = 8; off; off >>= 1)
            acc += __shfl_xor_sync(0xffffffffu, acc, off);
        if (lane == 0) y[(size_t)b * OUT + o] = acc;
    }
}

extern "C" void kernel_launch(void* const* d_in, const int* in_sizes, int n_in,
                              void* d_out, int out_size) {
    const float* x      = (const float*)d_in[0];  // [2048, 256]
    const float* affine = (const float*)d_in[1];  // [256, 256, 4]
    const float* mask   = (const float*)d_in[2];  // [256, 256]

    float* y    = (float*)d_out;                        // [2048, 256]
    float* post = (float*)d_out + (size_t)BATCH * OUT;  // [2048, 256, 256]

    kan_precompute<<<(OUT * IN) / (256 * 4), 256>>>((const float4*)affine,
                                                    (const float4*)mask);

    // PDL launch: kan_main begins launching while kan_precompute runs; the
    // in-kernel cudaGridDependencySynchronize() enforces the data dependency.
    cudaLaunchConfig_t cfg = {};
    cfg.gridDim = dim3(BATCH / BT, OUT / OT);   // (512, 16) = 8192 blocks
    cfg.blockDim = dim3(256, 1, 1);
    cfg.dynamicSmemBytes = 0;
    cfg.stream = 0;
    cudaLaunchAttribute attr[1];
    attr[0].id = cudaLaunchAttributeProgrammaticStreamSerialization;
    attr[0].val.programmaticStreamSerializationAllowed = 1;
    cfg.attrs = attr;
    cfg.numAttrs = 1;
    cudaLaunchKernelEx(&cfg, kan_main, x, y, post);
}

// round 14
// speedup vs baseline: 1.0779x; 1.0115x over previous
#include <cuda_runtime.h>

#define BATCH 2048
#define IN 256
#define OUT 256
#define OT 8    // outputs per block (32 lanes per output -> fewer coef regs)
#define BT 4    // batches per block

// Folded affine coefficients: postact = c1*x + c0
__device__ float g_c1[OUT * IN];
__device__ float g_c0[OUT * IN];

// Vectorized precompute: each thread folds 4 consecutive (o,i) elements.
__global__ __launch_bounds__(256) void kan_precompute(const float4* __restrict__ affine,
                                                      const float4* __restrict__ mask) {
    // Let the dependent kan_main launch immediately; its grid-dependency sync
    // still waits for this grid's completion before reading g_c1/g_c0.
    cudaTriggerProgrammaticLaunchCompletion();

    int v = blockIdx.x * blockDim.x + threadIdx.x;   // float4 index, 0..16383
    float4 m4 = mask[v];
    const float mm[4] = {m4.x, m4.y, m4.z, m4.w};
    float c1v[4], c0v[4];
#pragma unroll
    for (int q = 0; q < 4; q++) {
        float4 a = affine[4 * v + q];                // (a0,a1,a2,a3)
        c1v[q] = mm[q] * a.z * a.x;
        c0v[q] = mm[q] * fmaf(a.z, a.y, a.w);
    }
    reinterpret_cast<float4*>(g_c1)[v] = make_float4(c1v[0], c1v[1], c1v[2], c1v[3]);
    reinterpret_cast<float4*>(g_c0)[v] = make_float4(c0v[0], c0v[1], c0v[2], c0v[3]);
}

// 6 blocks/SM target: 48 warps resident (vs 32 before) for more store MLP.
__global__ __launch_bounds__(256, 6) void kan_main(const float* __restrict__ x,
                                                   float* __restrict__ y,
                                                   float* __restrict__ post) {
    __shared__ float4 xs[BT * (IN / 4)];  // 4 batches x 64 float4 = 4 KB

    const int t = threadIdx.x;
    const int o_loc = t >> 5;      // 0..7  (one full warp per output)
    const int lane = t & 31;       // 0..31
    const int o = blockIdx.y * OT + o_loc;
    const int b0 = blockIdx.x * BT;

    // x tile load does NOT depend on the precompute — do it before the grid
    // sync so it overlaps the tail of kan_precompute. 256 float4s, 1/thread.
    const float4* xg = reinterpret_cast<const float4*>(x + (size_t)b0 * IN);
    xs[t] = xg[t];

    // Wait for kan_precompute's grid to complete before reading g_c1/g_c0.
    cudaGridDependencySynchronize();
    __syncthreads();

    // This thread's 8-coefficient slice (2 float4 pairs), reused for all batches.
    float4 c1r[2], c0r[2];
#pragma unroll
    for (int k = 0; k < 2; k++) {
        int f = lane + 32 * k;     // float4 index within the row (0..63)
        c1r[k] = reinterpret_cast<const float4*>(g_c1)[o * (IN / 4) + f];
        c0r[k] = reinterpret_cast<const float4*>(g_c0)[o * (IN / 4) + f];
    }

#pragma unroll
    for (int bl = 0; bl < BT; bl++) {
        const int b = b0 + bl;
        float4* prow = reinterpret_cast<float4*>(post + ((size_t)b * OUT + o) * IN);
        float acc = 0.0f;
#pragma unroll
        for (int k = 0; k < 2; k++) {
            float4 xv = xs[bl * (IN / 4) + lane + 32 * k];
            float4 p;
            p.x = fmaf(c1r[k].x, xv.x, c0r[k].x);
            p.y = fmaf(c1r[k].y, xv.y, c0r[k].y);
            p.z = fmaf(c1r[k].z, xv.z, c0r[k].z);
            p.w = fmaf(c1r[k].w, xv.w, c0r[k].w);
            acc += (p.x + p.y) + (p.z + p.w);
            // 32 lanes with consecutive f -> contiguous 512B run, evict-first.
            __stcs(&prow[lane + 32 * k], p);
        }
        // Full-warp reduction for this output's row sum.
#pragma unroll
        for (int off = 16; off; off >>= 1)
            acc += __shfl_xor_sync(0xffffffffu, acc, off);
        if (lane == 0) y[(size_t)b * OUT + o] = acc;
    }
}

extern "C" void kernel_launch(void* const* d_in, const int* in_sizes, int n_in,
                              void* d_out, int out_size) {
    const float* x      = (const float*)d_in[0];  // [2048, 256]
    const float* affine = (const float*)d_in[1];  // [256, 256, 4]
    const float* mask   = (const float*)d_in[2];  // [256, 256]

    float* y    = (float*)d_out;                        // [2048, 256]
    float* post = (float*)d_out + (size_t)BATCH * OUT;  // [2048, 256, 256]

    kan_precompute<<<(OUT * IN) / (256 * 4), 256>>>((const float4*)affine,
                                                    (const float4*)mask);

    // PDL launch: kan_main begins launching while kan_precompute runs; the
    // in-kernel cudaGridDependencySynchronize() enforces the data dependency.
    cudaLaunchConfig_t cfg = {};
    cfg.gridDim = dim3(BATCH / BT, OUT / OT);   // (512, 32) = 16384 blocks
    cfg.blockDim = dim3(256, 1, 1);
    cfg.dynamicSmemBytes = 0;
    cfg.stream = 0;
    cudaLaunchAttribute attr[1];
    attr[0].id = cudaLaunchAttributeProgrammaticStreamSerialization;
    attr[0].val.programmaticStreamSerializationAllowed = 1;
    cfg.attrs = attr;
    cfg.numAttrs = 1;
    cudaLaunchKernelEx(&cfg, kan_main, x, y, post);
}

// round 15
// speedup vs baseline: 1.0797x; 1.0016x over previous
#include <cuda_runtime.h>

#define BATCH 2048
#define IN 256
#define OUT 256
#define OT 8    // outputs per block (one full warp per output)
#define BT 4    // batches per block

// Folded affine coefficients: postact = c1*x + c0
__device__ float g_c1[OUT * IN];
__device__ float g_c0[OUT * IN];

// Vectorized precompute: each thread folds 4 consecutive (o,i) elements.
__global__ __launch_bounds__(256) void kan_precompute(const float4* __restrict__ affine,
                                                      const float4* __restrict__ mask) {
    // Let the dependent kan_main launch immediately; its grid-dependency sync
    // still waits for this grid's completion before reading g_c1/g_c0.
    cudaTriggerProgrammaticLaunchCompletion();

    int v = blockIdx.x * blockDim.x + threadIdx.x;   // float4 index, 0..16383
    float4 m4 = mask[v];
    const float mm[4] = {m4.x, m4.y, m4.z, m4.w};
    float c1v[4], c0v[4];
#pragma unroll
    for (int q = 0; q < 4; q++) {
        float4 a = affine[4 * v + q];                // (a0,a1,a2,a3)
        c1v[q] = mm[q] * a.z * a.x;
        c0v[q] = mm[q] * fmaf(a.z, a.y, a.w);
    }
    reinterpret_cast<float4*>(g_c1)[v] = make_float4(c1v[0], c1v[1], c1v[2], c1v[3]);
    reinterpret_cast<float4*>(g_c0)[v] = make_float4(c0v[0], c0v[1], c0v[2], c0v[3]);
}

// Grid swapped vs R14: blockIdx.x = output slice (32), blockIdx.y = batch tile
// (512). Consecutively-launched blocks now write ADJACENT 8 KB chunks of the
// same batch region, making the concurrent DRAM write set dense contiguous
// 1 MB spans (better row-buffer locality) instead of 1 MB-strided scatter.
__global__ __launch_bounds__(256, 6) void kan_main(const float* __restrict__ x,
                                                   float* __restrict__ y,
                                                   float* __restrict__ post) {
    __shared__ float4 xs[BT * (IN / 4)];  // 4 batches x 64 float4 = 4 KB

    const int t = threadIdx.x;
    const int o_loc = t >> 5;      // 0..7  (one full warp per output)
    const int lane = t & 31;       // 0..31
    const int o = blockIdx.x * OT + o_loc;
    const int b0 = blockIdx.y * BT;

    // x tile load does NOT depend on the precompute — do it before the grid
    // sync so it overlaps the tail of kan_precompute. 256 float4s, 1/thread.
    const float4* xg = reinterpret_cast<const float4*>(x + (size_t)b0 * IN);
    xs[t] = xg[t];

    // Wait for kan_precompute's grid to complete before reading g_c1/g_c0.
    cudaGridDependencySynchronize();
    __syncthreads();

    // This thread's 8-coefficient slice (2 float4 pairs), reused for all batches.
    float4 c1r[2], c0r[2];
#pragma unroll
    for (int k = 0; k < 2; k++) {
        int f = lane + 32 * k;     // float4 index within the row (0..63)
        c1r[k] = reinterpret_cast<const float4*>(g_c1)[o * (IN / 4) + f];
        c0r[k] = reinterpret_cast<const float4*>(g_c0)[o * (IN / 4) + f];
    }

#pragma unroll
    for (int bl = 0; bl < BT; bl++) {
        const int b = b0 + bl;
        float4* prow = reinterpret_cast<float4*>(post + ((size_t)b * OUT + o) * IN);
        float acc = 0.0f;
#pragma unroll
        for (int k = 0; k < 2; k++) {
            float4 xv = xs[bl * (IN / 4) + lane + 32 * k];
            float4 p;
            p.x = fmaf(c1r[k].x, xv.x, c0r[k].x);
            p.y = fmaf(c1r[k].y, xv.y, c0r[k].y);
            p.z = fmaf(c1r[k].z, xv.z, c0r[k].z);
            p.w = fmaf(c1r[k].w, xv.w, c0r[k].w);
            acc += (p.x + p.y) + (p.z + p.w);
            // 32 lanes with consecutive f -> contiguous 512B run, evict-first.
            __stcs(&prow[lane + 32 * k], p);
        }
        // Full-warp reduction for this output's row sum.
#pragma unroll
        for (int off = 16; off; off >>= 1)
            acc += __shfl_xor_sync(0xffffffffu, acc, off);
        if (lane == 0) y[(size_t)b * OUT + o] = acc;
    }
}

extern "C" void kernel_launch(void* const* d_in, const int* in_sizes, int n_in,
                              void* d_out, int out_size) {
    const float* x      = (const float*)d_in[0];  // [2048, 256]
    const float* affine = (const float*)d_in[1];  // [256, 256, 4]
    const float* mask   = (const float*)d_in[2];  // [256, 256]

    float* y    = (float*)d_out;                        // [2048, 256]
    float* post = (float*)d_out + (size_t)BATCH * OUT;  // [2048, 256, 256]

    kan_precompute<<<(OUT * IN) / (256 * 4), 256>>>((const float4*)affine,
                                                    (const float4*)mask);

    // PDL launch: kan_main begins launching while kan_precompute runs; the
    // in-kernel cudaGridDependencySynchronize() enforces the data dependency.
    cudaLaunchConfig_t cfg = {};
    cfg.gridDim = dim3(OUT / OT, BATCH / BT);   // (32, 512) — o-major launch order
    cfg.blockDim = dim3(256, 1, 1);
    cfg.dynamicSmemBytes = 0;
    cfg.stream = 0;
    cudaLaunchAttribute attr[1];
    attr[0].id = cudaLaunchAttributeProgrammaticStreamSerialization;
    attr[0].val.programmaticStreamSerializationAllowed = 1;
    cfg.attrs = attr;
    cfg.numAttrs = 1;
    cudaLaunchKernelEx(&cfg, kan_main, x, y, post);
}